// round 8
// baseline (speedup 1.0000x reference)
#include <cuda_runtime.h>
#include <math.h>

#define TT    512
#define INSZ  512
#define HH    1024
#define OUTSZ 512
#define NG    4096
#define BSEL  63            // only batch row 63 affects the output
#define K0    1536          // INSZ + HH
#define K1    2048          // HH + HH
#define NBLK  128
#define NTHR  512
#define NBAR  514u

typedef unsigned long long ull;

// ---------------------------------------------------------------------------
// Static device scratch.
// ---------------------------------------------------------------------------
__device__ float    g_W1p[(size_t)NBLK * 32 * K1];   // packed layer-1 weights (33.6 MB)
__device__ float    g_h0[2][HH];                     // h0 ping-pong
__device__ float    g_h1init[HH];                    // initial h1
__device__ float    g_hist[TT][HH];                  // h1(t) history
__device__ unsigned g_flags[NBLK * 32];              // one 128B line per block
__device__ unsigned g_base = 0u;                     // persistent phase base

// Distributed grid barrier: per-block flag lines, scoped release/acquire.
__device__ __forceinline__ void gridbar(unsigned target) {
    __syncthreads();
    if (threadIdx.x == 0) {
        unsigned* f = &g_flags[blockIdx.x << 5];
        asm volatile("st.release.gpu.u32 [%0], %1;" :: "l"(f), "r"(target) : "memory");
    }
    if (threadIdx.x < NBLK) {
        unsigned* f = &g_flags[threadIdx.x << 5];
        unsigned v;
        do { asm volatile("ld.acquire.gpu.u32 %0, [%1];" : "=r"(v) : "l"(f) : "memory"); }
        while ((int)(v - target) < 0);
    }
    __syncthreads();
}

// packed fp32x2 FMA (sm_100+): 2 MACs per instruction, full fp32 precision
__device__ __forceinline__ void fma2(ull& a, ull x, ull w) {
    asm("fma.rn.f32x2 %0, %1, %2, %0;" : "+l"(a) : "l"(x), "l"(w));
}
__device__ __forceinline__ ull pk(float a, float b) {
    ull r; asm("mov.b64 %0, {%1, %2};" : "=l"(r) : "f"(a), "f"(b)); return r;
}
__device__ __forceinline__ float upk_sum(ull a) {
    float lo, hi; asm("mov.b64 {%0, %1}, %2;" : "=f"(lo), "=f"(hi) : "l"(a));
    return lo + hi;
}

__device__ __forceinline__ float sigf_(float x) {
    return __fdividef(1.0f, 1.0f + __expf(-x));
}
__device__ __forceinline__ float tanhf_(float x) {
    return 1.0f - __fdividef(2.0f, __expf(2.0f * x) + 1.0f);
}

// shfl-reduce 4 gate partials over the warp, then the LSTM cell update.
// All lanes compute identically (c replicated per lane); returns h.
__device__ __forceinline__ float cell_tail(ull a0, ull a1, ull a2, ull a3,
                                           float bi, float bj, float bf, float bo,
                                           float& c)
{
    float s0 = upk_sum(a0), s1 = upk_sum(a1), s2 = upk_sum(a2), s3 = upk_sum(a3);
#pragma unroll
    for (int o = 16; o; o >>= 1) {
        s0 += __shfl_xor_sync(0xffffffffu, s0, o);
        s1 += __shfl_xor_sync(0xffffffffu, s1, o);
        s2 += __shfl_xor_sync(0xffffffffu, s2, o);
        s3 += __shfl_xor_sync(0xffffffffu, s3, o);
    }
    float zi = s0 + bi, zj = s1 + bj, zf = s2 + bf + 1.0f, zo = s3 + bo;
    float cn = sigf_(zf) * c + sigf_(zi) * tanhf_(zj);
    c = cn;
    return sigf_(zo) * tanhf_(cn);
}

// SMEM: w0s (32 strips x 1536, XOR-swizzled) | in_sh (2560)
#define S_IN   (32 * K0)
#define S_TOTF (S_IN + 2560)

__global__ __launch_bounds__(NTHR, 1) void lstm_persistent(
    const float* __restrict__ X,
    const float* __restrict__ state,
    const float* __restrict__ W0, const float* __restrict__ b0,
    const float* __restrict__ W1, const float* __restrict__ b1,
    const float* __restrict__ Wd, const float* __restrict__ bd,
    float* __restrict__ out)
{
    extern __shared__ __align__(16) float sm[];
    float* w0s   = sm;
    float* in_sh = sm + S_IN;

    const int tid   = threadIdx.x;
    const int bid   = blockIdx.x;
    const int wid   = tid >> 5;
    const int lane  = tid & 31;
    const int hbase = bid << 3;
    const int jloc  = wid & 7;
    const int hcol  = hbase + jloc;

    const unsigned base = *(volatile unsigned*)&g_base;

    // ---- one-time: repack W0 -> SMEM [strip][k], XOR swizzle on k4 ----
    for (int e = tid; e < 32 * K0; e += NTHR) {
        int c = e & 31, k = e >> 5;
        int col = (c >> 3) * HH + hbase + (c & 7);
        int p4 = (k >> 2) ^ c;
        w0s[c * K0 + (p4 << 2) + (k & 3)] = __ldg(W0 + (size_t)k * NG + col);
    }
    // ---- one-time: repack W1 -> block-private GMEM [strip][k] ----
    float* W1pb = g_W1p + (size_t)bid * 32 * K1;
    for (int e = tid; e < 32 * K1; e += NTHR) {
        int c = e & 31, k = e >> 5;
        int col = (c >> 3) * HH + hbase + (c & 7);
        W1pb[c * K1 + k] = __ldg(W1 + (size_t)k * NG + col);
    }

    // ---- per-warp registers: gate biases + cell state (from state row 63) ----
    const float* srow = state + (size_t)BSEL * 4 * HH;
    const float* bsrc = (wid < 8) ? b0 : b1;
    float bi  = __ldg(bsrc + hcol);
    float bj  = __ldg(bsrc + HH + hcol);
    float bfv = __ldg(bsrc + 2 * HH + hcol);
    float bo  = __ldg(bsrc + 3 * HH + hcol);
    float creg = (wid < 8) ? __ldg(srow + hcol) : __ldg(srow + 2 * HH + hcol);

    if (tid < 8) {
        __stcg(&g_h0[1][hbase + tid],  __ldg(srow + HH + hbase + tid));
        __stcg(&g_h1init[hbase + tid], __ldg(srow + 3 * HH + hbase + tid));
    }
    gridbar(base + 1u);

    // strip indices for this warp's h-column (gates i,j,f,o)
    const int c0i = jloc, c1i = 8 + jloc, c2i = 16 + jloc, c3i = 24 + jloc;

    const float* Xrow = X + (size_t)BSEL * TT * INSZ;

    // ---- pipelined time loop: phase p = layer0(t=p) + layer1(t=p-1) ----
    for (int p = 0; p <= TT; p++) {
        const int rbuf = (p + 1) & 1, wbuf = p & 1;
        const float* h1src = (p == 1) ? g_h1init : g_hist[p >= 2 ? p - 2 : 0];

        // stage inputs: f4 [0:128)=x(p), [128:384)=h0(p-1), [384:640)=h1(p-2)
        for (int e = tid; e < 640; e += NTHR) {
            float4 v = make_float4(0.f, 0.f, 0.f, 0.f);
            if (e < 128) {
                if (p < TT) v = __ldg((const float4*)(Xrow + (size_t)p * INSZ) + e);
            } else if (e < 384) {
                v = __ldcg((const float4*)g_h0[rbuf] + (e - 128));
            } else if (p >= 1) {
                v = __ldcg((const float4*)h1src + (e - 384));
            }
            ((float4*)in_sh)[e] = v;
        }
        __syncthreads();

        if (wid < 8) {
            // ---- layer 0: warp owns hcol, 4 gate strips from SMEM ----
            if (p < TT) {
                ull a0 = 0, a1 = 0, a2 = 0, a3 = 0;
                const float* s0 = w0s + c0i * K0; const int l0 = lane ^ c0i;
                const float* s1 = w0s + c1i * K0; const int l1 = lane ^ c1i;
                const float* s2 = w0s + c2i * K0; const int l2 = lane ^ c2i;
                const float* s3 = w0s + c3i * K0; const int l3 = lane ^ c3i;
#pragma unroll 4
                for (int i = 0; i < 12; i++) {
                    ulonglong2 xv = *(const ulonglong2*)(in_sh + i * 128 + (lane << 2));
                    ulonglong2 w;
                    w = *(const ulonglong2*)(s0 + ((i * 32 + l0) << 2));
                    fma2(a0, xv.x, w.x); fma2(a0, xv.y, w.y);
                    w = *(const ulonglong2*)(s1 + ((i * 32 + l1) << 2));
                    fma2(a1, xv.x, w.x); fma2(a1, xv.y, w.y);
                    w = *(const ulonglong2*)(s2 + ((i * 32 + l2) << 2));
                    fma2(a2, xv.x, w.x); fma2(a2, xv.y, w.y);
                    w = *(const ulonglong2*)(s3 + ((i * 32 + l3) << 2));
                    fma2(a3, xv.x, w.x); fma2(a3, xv.y, w.y);
                }
                float h = cell_tail(a0, a1, a2, a3, bi, bj, bfv, bo, creg);
                if (lane == 0) __stcg(&g_h0[wbuf][hcol], h);
            }
        } else {
            // ---- layer 1: warp owns hcol, 4 gate strips streamed from L2 ----
            if (p >= 1) {
                ull a0 = 0, a1 = 0, a2 = 0, a3 = 0;
                const float* t0 = W1pb + c0i * K1;
                const float* t1 = W1pb + c1i * K1;
                const float* t2 = W1pb + c2i * K1;
                const float* t3 = W1pb + c3i * K1;
                const float* xp = in_sh + 512;
#pragma unroll 2
                for (int i = 0; i < 16; i++) {
                    const int off = i * 128 + (lane << 2);
                    ulonglong2 xv = *(const ulonglong2*)(xp + off);
                    float4 wf;
                    wf = __ldcg((const float4*)(t0 + off));
                    fma2(a0, xv.x, pk(wf.x, wf.y)); fma2(a0, xv.y, pk(wf.z, wf.w));
                    wf = __ldcg((const float4*)(t1 + off));
                    fma2(a1, xv.x, pk(wf.x, wf.y)); fma2(a1, xv.y, pk(wf.z, wf.w));
                    wf = __ldcg((const float4*)(t2 + off));
                    fma2(a2, xv.x, pk(wf.x, wf.y)); fma2(a2, xv.y, pk(wf.z, wf.w));
                    wf = __ldcg((const float4*)(t3 + off));
                    fma2(a3, xv.x, pk(wf.x, wf.y)); fma2(a3, xv.y, pk(wf.z, wf.w));
                }
                float h = cell_tail(a0, a1, a2, a3, bi, bj, bfv, bo, creg);
                if (lane == 0) __stcg(&g_hist[p - 1][hcol], h);
            }
        }
        gridbar(base + 2u + (unsigned)p);
    }

    // ---- dense: out[t][o] = hist[t] @ Wd + bd; block owns 4 t-rows ----
    {
        float* hst = sm;                 // reuse w0s region (4096 floats)
        int t0q = bid << 2;
        for (int e = tid; e < 1024; e += NTHR)
            ((float4*)hst)[e] = __ldcg((const float4*)g_hist[t0q + (e >> 8)] + (e & 255));
        __syncthreads();

        int r  = tid >> 7;               // 0..3
        int o0 = (tid & 127) << 2;       // 0..508
        float4 acc = make_float4(__ldg(bd + o0), __ldg(bd + o0 + 1),
                                 __ldg(bd + o0 + 2), __ldg(bd + o0 + 3));
        const float* hrow = hst + (r << 10);
        const float* wp = Wd + o0;
#pragma unroll 8
        for (int k = 0; k < HH; k++) {
            float4 w4 = __ldcg((const float4*)wp);
            wp += OUTSZ;
            acc.x = fmaf(hrow[k], w4.x, acc.x);
            acc.y = fmaf(hrow[k], w4.y, acc.y);
            acc.z = fmaf(hrow[k], w4.z, acc.z);
            acc.w = fmaf(hrow[k], w4.w, acc.w);
        }
        *(float4*)(out + (size_t)(t0q + r) * OUTSZ + o0) = acc;
    }

    // advance the persistent phase base for the next graph replay
    if (bid == 0 && tid == 0)
        *(volatile unsigned*)&g_base = base + NBAR;
}

// ---------------------------------------------------------------------------
// Launcher: ONE kernel launch, >48KB dynamic smem opted in.
// ---------------------------------------------------------------------------
extern "C" void kernel_launch(void* const* d_in, const int* in_sizes, int n_in,
                              void* d_out, int out_size)
{
    (void)in_sizes; (void)n_in; (void)out_size;
    const float* X     = (const float*)d_in[0];
    const float* state = (const float*)d_in[1];
    const float* W0    = (const float*)d_in[2];
    const float* b0    = (const float*)d_in[3];
    const float* W1    = (const float*)d_in[4];
    const float* b1    = (const float*)d_in[5];
    const float* Wd    = (const float*)d_in[6];
    const float* bd    = (const float*)d_in[7];

    static int configured = 0;
    if (!configured) {
        cudaFuncSetAttribute(lstm_persistent,
                             cudaFuncAttributeMaxDynamicSharedMemorySize,
                             S_TOTF * sizeof(float));
        configured = 1;
    }

    lstm_persistent<<<NBLK, NTHR, S_TOTF * sizeof(float)>>>(
        X, state, W0, b0, W1, b1, Wd, bd, (float*)d_out);
}

// round 9
// speedup vs baseline: 1.0851x; 1.0851x over previous
#include <cuda_runtime.h>
#include <cuda_fp16.h>
#include <math.h>

#define TT    512
#define INSZ  512
#define HH    1024
#define OUTSZ 512
#define NG    4096
#define BSEL  63            // only batch row 63 affects the output
#define NBLK  128
#define NTHR  512
#define NBAR  514u

typedef unsigned long long ull;

// ---------------------------------------------------------------------------
// Static device scratch (no per-phase weight traffic: weights live in SMEM).
// ---------------------------------------------------------------------------
__device__ __align__(16) float g_h0[2][HH];       // h0 ping-pong
__device__ __align__(16) float g_h1init[HH];      // initial h1
__device__ __align__(16) float g_hist[TT][HH];    // h1(t) history
__device__ unsigned g_flags[NBLK * 32];           // one 128B line per block
__device__ unsigned g_base = 0u;                  // persistent phase base

// Distributed grid barrier: per-block flag lines, scoped release/acquire.
__device__ __forceinline__ void gridbar(unsigned target) {
    __syncthreads();
    if (threadIdx.x == 0) {
        unsigned* f = &g_flags[blockIdx.x << 5];
        asm volatile("st.release.gpu.u32 [%0], %1;" :: "l"(f), "r"(target) : "memory");
    }
    if (threadIdx.x < NBLK) {
        unsigned* f = &g_flags[threadIdx.x << 5];
        unsigned v;
        do { asm volatile("ld.acquire.gpu.u32 %0, [%1];" : "=r"(v) : "l"(f) : "memory"); }
        while ((int)(v - target) < 0);
    }
    __syncthreads();
}

// packed fp32x2 FMA (sm_100+)
__device__ __forceinline__ void fma2(ull& a, ull x, ull w) {
    asm("fma.rn.f32x2 %0, %1, %2, %0;" : "+l"(a) : "l"(x), "l"(w));
}
__device__ __forceinline__ ull pk(float a, float b) {
    ull r; asm("mov.b64 %0, {%1, %2};" : "=l"(r) : "f"(a), "f"(b)); return r;
}
__device__ __forceinline__ ull h2f2(__half2 h) {
    float2 f = __half22float2(h);
    return pk(f.x, f.y);
}
__device__ __forceinline__ float upk_sum(ull a) {
    float lo, hi; asm("mov.b64 {%0, %1}, %2;" : "=f"(lo), "=f"(hi) : "l"(a));
    return lo + hi;
}

__device__ __forceinline__ float sigf_(float x) {
    return __fdividef(1.0f, 1.0f + __expf(-x));
}
__device__ __forceinline__ float tanhf_(float x) {
    return 1.0f - __fdividef(2.0f, __expf(2.0f * x) + 1.0f);
}

// shfl-reduce 4 gate partials over the warp, then the LSTM cell update.
__device__ __forceinline__ float cell_tail(ull a0, ull a1, ull a2, ull a3,
                                           float bi, float bj, float bf, float bo,
                                           float& c)
{
    float s0 = upk_sum(a0), s1 = upk_sum(a1), s2 = upk_sum(a2), s3 = upk_sum(a3);
#pragma unroll
    for (int o = 16; o; o >>= 1) {
        s0 += __shfl_xor_sync(0xffffffffu, s0, o);
        s1 += __shfl_xor_sync(0xffffffffu, s1, o);
        s2 += __shfl_xor_sync(0xffffffffu, s2, o);
        s3 += __shfl_xor_sync(0xffffffffu, s3, o);
    }
    float zi = s0 + bi, zj = s1 + bj, zf = s2 + bf + 1.0f, zo = s3 + bo;
    float cn = sigf_(zf) * c + sigf_(zi) * tanhf_(zj);
    c = cn;
    return sigf_(zo) * tanhf_(cn);
}

// SMEM (bytes): W0 fp16 [strip][k] 32x1536 = 98304 | W1 fp16 32x2048 = 131072
#define SM_W0   0
#define SM_W1   98304
#define SM_TOT  229376

__global__ __launch_bounds__(NTHR, 1) void lstm_persistent(
    const float* __restrict__ X,
    const float* __restrict__ state,
    const float* __restrict__ W0, const float* __restrict__ b0,
    const float* __restrict__ W1, const float* __restrict__ b1,
    const float* __restrict__ Wd, const float* __restrict__ bd,
    float* __restrict__ out)
{
    extern __shared__ __align__(16) unsigned char smraw[];
    __half* w0h = (__half*)(smraw + SM_W0);
    __half* w1h = (__half*)(smraw + SM_W1);

    const int tid   = threadIdx.x;
    const int bid   = blockIdx.x;
    const int wid   = tid >> 5;
    const int lane  = tid & 31;
    const int hbase = bid << 3;
    const int jloc  = wid & 7;
    const int hcol  = hbase + jloc;

    const unsigned base = *(volatile unsigned*)&g_base;

    // ---- one-time: pack weights -> SMEM fp16, [strip c][k] ----
    for (int e = tid; e < 32 * 1536; e += NTHR) {
        int c = e & 31, k = e >> 5;
        int col = (c >> 3) * HH + hbase + (c & 7);
        w0h[c * 1536 + k] = __float2half_rn(__ldg(W0 + (size_t)k * NG + col));
    }
    for (int e = tid; e < 32 * 2048; e += NTHR) {
        int c = e & 31, k = e >> 5;
        int col = (c >> 3) * HH + hbase + (c & 7);
        w1h[c * 2048 + k] = __float2half_rn(__ldg(W1 + (size_t)k * NG + col));
    }

    // ---- per-warp registers: biases + cell state (state row 63) ----
    const float* srow = state + (size_t)BSEL * 4 * HH;
    const float* bsrc = (wid < 8) ? b0 : b1;
    float bi  = __ldg(bsrc + hcol);
    float bj  = __ldg(bsrc + HH + hcol);
    float bfv = __ldg(bsrc + 2 * HH + hcol);
    float bo  = __ldg(bsrc + 3 * HH + hcol);
    float creg = (wid < 8) ? __ldg(srow + hcol) : __ldg(srow + 2 * HH + hcol);

    if (tid < 8) {
        __stcg(&g_h0[1][hbase + tid],  __ldg(srow + HH + hbase + tid));
        __stcg(&g_h1init[hbase + tid], __ldg(srow + 3 * HH + hbase + tid));
    }
    gridbar(base + 1u);

    const int c0i = jloc, c1i = 8 + jloc, c2i = 16 + jloc, c3i = 24 + jloc;
    const float* Xrow = X + (size_t)BSEL * TT * INSZ;

    // ---- pipelined time loop: phase p = layer0(t=p) + layer1(t=p-1) ----
    for (int p = 0; p <= TT; p++) {
        const int rbuf = (p + 1) & 1, wbuf = p & 1;

        if (wid < 8) {
            // ---- layer 0: gates from SMEM fp16; x from L2(RO), h0 via ldcg ----
            if (p < TT) {
                const __half2* s0 = (const __half2*)w0h + c0i * 768;
                const __half2* s1 = (const __half2*)w0h + c1i * 768;
                const __half2* s2 = (const __half2*)w0h + c2i * 768;
                const __half2* s3 = (const __half2*)w0h + c3i * 768;
                ull a0 = 0, a1 = 0, a2 = 0, a3 = 0;
                const ull* xp = (const ull*)(Xrow + (size_t)p * INSZ);
#pragma unroll
                for (int i = 0; i < 8; i++) {            // k = 0..511 (x part)
                    int idx = lane + (i << 5);
                    ull xv = __ldg(xp + idx);
                    fma2(a0, xv, h2f2(s0[idx]));
                    fma2(a1, xv, h2f2(s1[idx]));
                    fma2(a2, xv, h2f2(s2[idx]));
                    fma2(a3, xv, h2f2(s3[idx]));
                }
                const ull* hp = (const ull*)g_h0[rbuf];
#pragma unroll
                for (int i = 0; i < 16; i++) {           // k = 512..1535 (h part)
                    int idx = lane + (i << 5);
                    ull xv = __ldcg(hp + idx);
                    fma2(a0, xv, h2f2(s0[256 + idx]));
                    fma2(a1, xv, h2f2(s1[256 + idx]));
                    fma2(a2, xv, h2f2(s2[256 + idx]));
                    fma2(a3, xv, h2f2(s3[256 + idx]));
                }
                float h = cell_tail(a0, a1, a2, a3, bi, bj, bfv, bo, creg);
                if (lane == 0) __stcg(&g_h0[wbuf][hcol], h);
            }
        } else {
            // ---- layer 1: gates from SMEM fp16; h0(p-1), h1(p-2) via ldcg ----
            if (p >= 1) {
                const float* h1src = (p == 1) ? g_h1init : g_hist[p - 2];
                const __half2* s0 = (const __half2*)w1h + c0i * 1024;
                const __half2* s1 = (const __half2*)w1h + c1i * 1024;
                const __half2* s2 = (const __half2*)w1h + c2i * 1024;
                const __half2* s3 = (const __half2*)w1h + c3i * 1024;
                ull a0 = 0, a1 = 0, a2 = 0, a3 = 0;
                const ull* hp0 = (const ull*)g_h0[rbuf];
#pragma unroll
                for (int i = 0; i < 16; i++) {           // k = 0..1023 (h0 part)
                    int idx = lane + (i << 5);
                    ull xv = __ldcg(hp0 + idx);
                    fma2(a0, xv, h2f2(s0[idx]));
                    fma2(a1, xv, h2f2(s1[idx]));
                    fma2(a2, xv, h2f2(s2[idx]));
                    fma2(a3, xv, h2f2(s3[idx]));
                }
                const ull* hp1 = (const ull*)h1src;
#pragma unroll
                for (int i = 0; i < 16; i++) {           // k = 1024..2047 (h1 part)
                    int idx = lane + (i << 5);
                    ull xv = __ldcg(hp1 + idx);
                    fma2(a0, xv, h2f2(s0[512 + idx]));
                    fma2(a1, xv, h2f2(s1[512 + idx]));
                    fma2(a2, xv, h2f2(s2[512 + idx]));
                    fma2(a3, xv, h2f2(s3[512 + idx]));
                }
                float h = cell_tail(a0, a1, a2, a3, bi, bj, bfv, bo, creg);
                if (lane == 0) __stcg(&g_hist[p - 1][hcol], h);
            }
        }
        gridbar(base + 2u + (unsigned)p);
    }

    // ---- dense: out[t][o] = hist[t] @ Wd + bd; block owns 4 t-rows ----
    {
        float* hst = (float*)smraw;          // reuse weight region (16KB)
        int t0q = bid << 2;
        for (int e = tid; e < 1024; e += NTHR)
            ((float4*)hst)[e] = __ldcg((const float4*)g_hist[t0q + (e >> 8)] + (e & 255));
        __syncthreads();

        int r  = tid >> 7;                   // 0..3
        int o0 = (tid & 127) << 2;           // 0..508
        float4 acc = make_float4(__ldg(bd + o0), __ldg(bd + o0 + 1),
                                 __ldg(bd + o0 + 2), __ldg(bd + o0 + 3));
        const float* hrow = hst + (r << 10);
        const float* wp = Wd + o0;
#pragma unroll 8
        for (int k = 0; k < HH; k++) {
            float4 w4 = __ldcg((const float4*)wp);
            wp += OUTSZ;
            acc.x = fmaf(hrow[k], w4.x, acc.x);
            acc.y = fmaf(hrow[k], w4.y, acc.y);
            acc.z = fmaf(hrow[k], w4.z, acc.z);
            acc.w = fmaf(hrow[k], w4.w, acc.w);
        }
        *(float4*)(out + (size_t)(t0q + r) * OUTSZ + o0) = acc;
    }

    // advance the persistent phase base for the next graph replay
    if (bid == 0 && tid == 0)
        *(volatile unsigned*)&g_base = base + NBAR;
}

// ---------------------------------------------------------------------------
// Launcher: ONE kernel launch, 224KB dynamic smem opted in.
// ---------------------------------------------------------------------------
extern "C" void kernel_launch(void* const* d_in, const int* in_sizes, int n_in,
                              void* d_out, int out_size)
{
    (void)in_sizes; (void)n_in; (void)out_size;
    const float* X     = (const float*)d_in[0];
    const float* state = (const float*)d_in[1];
    const float* W0    = (const float*)d_in[2];
    const float* b0    = (const float*)d_in[3];
    const float* W1    = (const float*)d_in[4];
    const float* b1    = (const float*)d_in[5];
    const float* Wd    = (const float*)d_in[6];
    const float* bd    = (const float*)d_in[7];

    static int configured = 0;
    if (!configured) {
        cudaFuncSetAttribute(lstm_persistent,
                             cudaFuncAttributeMaxDynamicSharedMemorySize,
                             SM_TOT);
        configured = 1;
    }

    lstm_persistent<<<NBLK, NTHR, SM_TOT>>>(
        X, state, W0, b0, W1, b1, Wd, bd, (float*)d_out);
}

// round 10
// speedup vs baseline: 1.1624x; 1.0713x over previous
#include <cuda_runtime.h>
#include <cuda_fp16.h>

#define TT    512
#define INSZ  512
#define HH    1024
#define OUTSZ 512
#define NG    4096
#define BSEL  63            // only batch row 63 affects the output
#define NBLK  128
#define NTHR  512

typedef unsigned long long ull;

// ---------------------------------------------------------------------------
// Static device scratch. Full h histories -> no ping-pong hazards, L1 may lag.
// ---------------------------------------------------------------------------
__device__ __align__(16) float g_h0h[TT + 1][HH];   // h0h[0] = init, h0h[p+1] = h0(p)
__device__ __align__(16) float g_h1h[TT + 1][HH];   // h1h[0] = init, h1h[t+1] = h1(t)
__device__ unsigned g_c0[TT][32];                   // per-phase counters (128B apart)
__device__ unsigned g_c1[TT][32];
__device__ unsigned g_flags[NBLK * 32];             // init barrier flags
__device__ unsigned g_base = 0u;                    // init-barrier base (+=2/replay)
__device__ unsigned g_rep  = 0u;                    // counter base (+=128/replay)

// init-only distributed grid barrier (scoped release/acquire)
__device__ __forceinline__ void gridbar(unsigned target) {
    __syncthreads();
    if (threadIdx.x == 0) {
        unsigned* f = &g_flags[blockIdx.x << 5];
        asm volatile("st.release.gpu.u32 [%0], %1;" :: "l"(f), "r"(target) : "memory");
    }
    if (threadIdx.x < NBLK) {
        unsigned* f = &g_flags[threadIdx.x << 5];
        unsigned v;
        do { asm volatile("ld.acquire.gpu.u32 %0, [%1];" : "=r"(v) : "l"(f) : "memory"); }
        while ((int)(v - target) < 0);
    }
    __syncthreads();
}

__device__ __forceinline__ void poll_ctr(unsigned* c, unsigned target) {
    unsigned v;
    do { asm volatile("ld.acquire.gpu.u32 %0, [%1];" : "=r"(v) : "l"(c) : "memory"); }
    while ((int)(v - target) < 0);
}
__device__ __forceinline__ void bump_ctr(unsigned* c) {
    asm volatile("red.release.gpu.global.add.u32 [%0], 1;" :: "l"(c) : "memory");
}

// packed fp32x2 FMA (sm_100+)
__device__ __forceinline__ void fma2(ull& a, ull x, ull w) {
    asm("fma.rn.f32x2 %0, %1, %2, %0;" : "+l"(a) : "l"(x), "l"(w));
}
__device__ __forceinline__ ull pk(float a, float b) {
    ull r; asm("mov.b64 %0, {%1, %2};" : "=l"(r) : "f"(a), "f"(b)); return r;
}
__device__ __forceinline__ ull h2f2(__half2 h) {
    float2 f = __half22float2(h);
    return pk(f.x, f.y);
}
__device__ __forceinline__ float upk_sum(ull a) {
    float lo, hi; asm("mov.b64 {%0, %1}, %2;" : "=f"(lo), "=f"(hi) : "l"(a));
    return lo + hi;
}
__device__ __forceinline__ float sigf_(float x) {
    return __fdividef(1.0f, 1.0f + __expf(-x));
}
__device__ __forceinline__ float tanhf_(float x) {
    return 1.0f - __fdividef(2.0f, __expf(2.0f * x) + 1.0f);
}

// shfl-reduce 4 gate partials over the warp, then the LSTM cell update.
__device__ __forceinline__ float cell_tail(ull a0, ull a1, ull a2, ull a3,
                                           float bi, float bj, float bf, float bo,
                                           float& c)
{
    float s0 = upk_sum(a0), s1 = upk_sum(a1), s2 = upk_sum(a2), s3 = upk_sum(a3);
#pragma unroll
    for (int o = 16; o; o >>= 1) {
        s0 += __shfl_xor_sync(0xffffffffu, s0, o);
        s1 += __shfl_xor_sync(0xffffffffu, s1, o);
        s2 += __shfl_xor_sync(0xffffffffu, s2, o);
        s3 += __shfl_xor_sync(0xffffffffu, s3, o);
    }
    float zi = s0 + bi, zj = s1 + bj, zf = s2 + bf + 1.0f, zo = s3 + bo;
    float cn = sigf_(zf) * c + sigf_(zi) * tanhf_(zj);
    c = cn;
    return sigf_(zo) * tanhf_(cn);
}

// SMEM (bytes): W0 fp16 [strip][k] 32x1536 | W1 fp16 32x2048 = 224 KB
#define SM_W0   0
#define SM_W1   98304
#define SM_TOT  229376

__global__ __launch_bounds__(NTHR, 1) void lstm_persistent(
    const float* __restrict__ X,
    const float* __restrict__ state,
    const float* __restrict__ W0, const float* __restrict__ b0,
    const float* __restrict__ W1, const float* __restrict__ b1,
    const float* __restrict__ Wd, const float* __restrict__ bd,
    float* __restrict__ out)
{
    extern __shared__ __align__(16) unsigned char smraw[];
    __half* w0h = (__half*)(smraw + SM_W0);
    __half* w1h = (__half*)(smraw + SM_W1);

    const int tid   = threadIdx.x;
    const int bid   = blockIdx.x;
    const int wid   = tid >> 5;
    const int lane  = tid & 31;
    const int hbase = bid << 3;
    const int jloc  = wid & 7;
    const int hcol  = hbase + jloc;

    const unsigned base = *(volatile unsigned*)&g_base;
    const unsigned rep  = *(volatile unsigned*)&g_rep;
    const unsigned FULL = rep + (unsigned)NBLK;

    // ---- one-time: pack weights -> SMEM fp16, [strip c][k] ----
    for (int e = tid; e < 32 * 1536; e += NTHR) {
        int c = e & 31, k = e >> 5;
        int col = (c >> 3) * HH + hbase + (c & 7);
        w0h[c * 1536 + k] = __float2half_rn(__ldg(W0 + (size_t)k * NG + col));
    }
    for (int e = tid; e < 32 * 2048; e += NTHR) {
        int c = e & 31, k = e >> 5;
        int col = (c >> 3) * HH + hbase + (c & 7);
        w1h[c * 2048 + k] = __float2half_rn(__ldg(W1 + (size_t)k * NG + col));
    }

    // ---- per-warp registers: biases + cell state (state row 63) ----
    const float* srow = state + (size_t)BSEL * 4 * HH;
    const float* bsrc = (wid < 8) ? b0 : b1;
    float bi  = __ldg(bsrc + hcol);
    float bj  = __ldg(bsrc + HH + hcol);
    float bfv = __ldg(bsrc + 2 * HH + hcol);
    float bo  = __ldg(bsrc + 3 * HH + hcol);
    float creg = (wid < 8) ? __ldg(srow + hcol) : __ldg(srow + 2 * HH + hcol);

    if (tid < 8) {
        __stcg(&g_h0h[0][hbase + tid], __ldg(srow + HH + hbase + tid));
        __stcg(&g_h1h[0][hbase + tid], __ldg(srow + 3 * HH + hbase + tid));
    }
    gridbar(base + 1u);   // initial h0h[0]/h1h[0] globally visible

    const int c0i = jloc, c1i = 8 + jloc, c2i = 16 + jloc, c3i = 24 + jloc;
    const float* Xrow = X + (size_t)BSEL * TT * INSZ;

    if (wid < 8) {
        // =================== layer-0 chain (warps 0-7) ===================
        const __half2* s0 = (const __half2*)w0h + c0i * 768;
        const __half2* s1 = (const __half2*)w0h + c1i * 768;
        const __half2* s2 = (const __half2*)w0h + c2i * 768;
        const __half2* s3 = (const __half2*)w0h + c3i * 768;
        for (int p = 0; p < TT; p++) {
            // x-part: independent of other blocks -> overlaps producer wait
            ull a0 = 0, a1 = 0, a2 = 0, a3 = 0;
            const ull* xp = (const ull*)(Xrow + (size_t)p * INSZ);
#pragma unroll
            for (int i = 0; i < 8; i++) {
                int idx = lane + (i << 5);
                ull xv = __ldg(xp + idx);
                fma2(a0, xv, h2f2(s0[idx]));
                fma2(a1, xv, h2f2(s1[idx]));
                fma2(a2, xv, h2f2(s2[idx]));
                fma2(a3, xv, h2f2(s3[idx]));
            }
            // wait for h0(p-1) from all blocks
            if (p > 0 && tid == 0) poll_ctr(&g_c0[p - 1][0], FULL);
            asm volatile("bar.sync 1, 256;" ::: "memory");
            const ull* hp = (const ull*)g_h0h[p];
#pragma unroll
            for (int i = 0; i < 16; i++) {
                int idx = lane + (i << 5);
                ull xv = __ldcg(hp + idx);
                fma2(a0, xv, h2f2(s0[256 + idx]));
                fma2(a1, xv, h2f2(s1[256 + idx]));
                fma2(a2, xv, h2f2(s2[256 + idx]));
                fma2(a3, xv, h2f2(s3[256 + idx]));
            }
            float h = cell_tail(a0, a1, a2, a3, bi, bj, bfv, bo, creg);
            if (lane == 0) __stcg(&g_h0h[p + 1][hcol], h);
            asm volatile("bar.sync 1, 256;" ::: "memory");
            if (tid == 0) bump_ctr(&g_c0[p][0]);
        }
    } else {
        // =================== layer-1 chain (warps 8-15) ==================
        const __half2* s0 = (const __half2*)w1h + c0i * 1024;
        const __half2* s1 = (const __half2*)w1h + c1i * 1024;
        const __half2* s2 = (const __half2*)w1h + c2i * 1024;
        const __half2* s3 = (const __half2*)w1h + c3i * 1024;
        for (int t = 0; t < TT; t++) {
            if (tid == 256) {
                poll_ctr(&g_c0[t][0], FULL);                 // h0(t) ready
                if (t > 0) poll_ctr(&g_c1[t - 1][0], FULL);  // h1(t-1) ready
            }
            asm volatile("bar.sync 2, 256;" ::: "memory");
            ull a0 = 0, a1 = 0, a2 = 0, a3 = 0;
            const ull* hp0 = (const ull*)g_h0h[t + 1];
#pragma unroll
            for (int i = 0; i < 16; i++) {
                int idx = lane + (i << 5);
                ull xv = __ldcg(hp0 + idx);
                fma2(a0, xv, h2f2(s0[idx]));
                fma2(a1, xv, h2f2(s1[idx]));
                fma2(a2, xv, h2f2(s2[idx]));
                fma2(a3, xv, h2f2(s3[idx]));
            }
            const ull* hp1 = (const ull*)g_h1h[t];
#pragma unroll
            for (int i = 0; i < 16; i++) {
                int idx = lane + (i << 5);
                ull xv = __ldcg(hp1 + idx);
                fma2(a0, xv, h2f2(s0[512 + idx]));
                fma2(a1, xv, h2f2(s1[512 + idx]));
                fma2(a2, xv, h2f2(s2[512 + idx]));
                fma2(a3, xv, h2f2(s3[512 + idx]));
            }
            float h = cell_tail(a0, a1, a2, a3, bi, bj, bfv, bo, creg);
            if (lane == 0) __stcg(&g_h1h[t + 1][hcol], h);
            asm volatile("bar.sync 2, 256;" ::: "memory");
            if (tid == 256) bump_ctr(&g_c1[t][0]);
        }
    }

    // ---- global completion of layer-1 before the dense tail ----
    if (tid == 0) poll_ctr(&g_c1[TT - 1][0], FULL);
    __syncthreads();

    // ---- dense: out[t][o] = h1(t) @ Wd + bd; block owns 4 t-rows ----
    {
        float* hst = (float*)smraw;          // reuse weight region (16KB)
        int t0q = bid << 2;
        for (int e = tid; e < 1024; e += NTHR)
            ((float4*)hst)[e] =
                __ldcg((const float4*)g_h1h[t0q + (e >> 8) + 1] + (e & 255));
        __syncthreads();

        int r  = tid >> 7;                   // 0..3
        int o0 = (tid & 127) << 2;           // 0..508
        float4 acc = make_float4(__ldg(bd + o0), __ldg(bd + o0 + 1),
                                 __ldg(bd + o0 + 2), __ldg(bd + o0 + 3));
        const float* hrow = hst + (r << 10);
        const float* wp = Wd + o0;
#pragma unroll 8
        for (int k = 0; k < HH; k++) {
            float4 w4 = __ldcg((const float4*)wp);
            wp += OUTSZ;
            acc.x = fmaf(hrow[k], w4.x, acc.x);
            acc.y = fmaf(hrow[k], w4.y, acc.y);
            acc.z = fmaf(hrow[k], w4.z, acc.z);
            acc.w = fmaf(hrow[k], w4.w, acc.w);
        }
        *(float4*)(out + (size_t)(t0q + r) * OUTSZ + o0) = acc;
    }

    // advance persistent bases for the next graph replay
    if (bid == 0 && tid == 0) {
        *(volatile unsigned*)&g_rep  = rep + (unsigned)NBLK;
        *(volatile unsigned*)&g_base = base + 2u;
    }
}

// ---------------------------------------------------------------------------
// Launcher: ONE kernel launch, 224KB dynamic smem opted in.
// ---------------------------------------------------------------------------
extern "C" void kernel_launch(void* const* d_in, const int* in_sizes, int n_in,
                              void* d_out, int out_size)
{
    (void)in_sizes; (void)n_in; (void)out_size;
    const float* X     = (const float*)d_in[0];
    const float* state = (const float*)d_in[1];
    const float* W0    = (const float*)d_in[2];
    const float* b0    = (const float*)d_in[3];
    const float* W1    = (const float*)d_in[4];
    const float* b1    = (const float*)d_in[5];
    const float* Wd    = (const float*)d_in[6];
    const float* bd    = (const float*)d_in[7];

    static int configured = 0;
    if (!configured) {
        cudaFuncSetAttribute(lstm_persistent,
                             cudaFuncAttributeMaxDynamicSharedMemorySize,
                             SM_TOT);
        configured = 1;
    }

    lstm_persistent<<<NBLK, NTHR, SM_TOT>>>(
        X, state, W0, b0, W1, b1, Wd, bd, (float*)d_out);
}